// round 15
// baseline (speedup 1.0000x reference)
#include <cuda_runtime.h>
#include <cuda_bf16.h>
#include <math.h>
#include <stdint.h>

// ---------------------------------------------------------------------------
// Problem constants
// ---------------------------------------------------------------------------
#define BQ 256
#define DQ 511
#define HQ 5120
#define KP1 512                 // padded K, layer 1
#define NQ2 512                 // padded N, layer 2
#define SPLITK1 2
#define SPLITK2 16
#define SPP1 (KP1 / SPLITK1 / 64)   // 4 stages per pass (gemm1)
#define SPP2 (HQ / SPLITK2 / 64)    // 5 stages per pass (gemm2)
#define QSPLIT 8

// ---------------------------------------------------------------------------
// Scratch (__device__ globals; no allocation allowed). Packed layout: [hi|lo].
// ---------------------------------------------------------------------------
__device__ __align__(16) __nv_bfloat16 g_a1p[BQ * 2 * KP1];
__device__ __align__(16) __nv_bfloat16 g_b1p[(size_t)HQ * 2 * KP1];
__device__ __align__(16) float         g_p1[(size_t)SPLITK1 * BQ * HQ];   // [z][m][n]
__device__ __align__(16) __nv_bfloat16 g_a2p[(size_t)BQ * 2 * HQ];
__device__ __align__(16) __nv_bfloat16 g_b2p[(size_t)NQ2 * 2 * HQ];
__device__ __align__(16) float         g_p2[(size_t)SPLITK2 * BQ * NQ2];  // [z][m][n]
__device__ __align__(16) float         g_phi[BQ * DQ];
__device__ float g_quadpart[BQ * QSPLIT];

#define SWZ(o) ((o) ^ (((o) >> 3) & 0x70))

__device__ __forceinline__ uint32_t smem_u32(const void* p) {
    uint32_t a;
    asm("{ .reg .u64 t; cvta.to.shared.u64 t, %1; cvt.u32.u64 %0, t; }"
        : "=r"(a) : "l"(p));
    return a;
}

// ---------------------------------------------------------------------------
// pack_split: fp32 -> [hi|lo] bf16 segments, 8 elems/thread, 16B stores.
// ---------------------------------------------------------------------------
__global__ void pack_split(const float* __restrict__ src, __nv_bfloat16* __restrict__ dst,
                           int nrows, int vrows, int K, int Kp) {
    const int n8 = Kp >> 3;
    const int idx = blockIdx.x * 256 + threadIdx.x;
    if (idx >= nrows * n8) return;
    const int r = idx / n8, c8 = (idx - r * n8) << 3;

    __align__(16) __nv_bfloat16 hb[8], lb[8];
#pragma unroll
    for (int t = 0; t < 8; ++t) {
        const int c = c8 + t;
        const float v = (r < vrows && c < K) ? src[(size_t)r * K + c] : 0.f;
        hb[t] = __float2bfloat16(v);
        lb[t] = __float2bfloat16(v - __bfloat162float(hb[t]));
    }
    const size_t base = (size_t)r * 2 * Kp;
    *(uint4*)&dst[base + c8]      = *(uint4*)hb;
    *(uint4*)&dst[base + Kp + c8] = *(uint4*)lb;
}

// ---------------------------------------------------------------------------
// gemm_mma: D[m][n] = sum_k A[m][k]*B[n][k] with bf16-split 3-pass schedule:
//   pass0 Ah*Bh, pass1 Ah*Bl, pass2 Al*Bh   (A,B stored [hi|lo], seg len Kp)
// Block tile 128m x 64n x 64k, 8 warps, double-buffered smem.
// occ=3: 48KB smem/CTA -> 144KB/SM; both launch grids (320, 256 CTAs) are
// fully resident in ONE wave -> no wave quantization.
// ---------------------------------------------------------------------------
__global__ __launch_bounds__(256, 3)
void gemm_mma(const __nv_bfloat16* __restrict__ A, const __nv_bfloat16* __restrict__ B,
              float* __restrict__ out, int kstride, int Kp, int spp,
              int zchunk, int out_ld, size_t zstride) {
    __shared__ __align__(1024) uint8_t smA[2][16384];   // 128 x 64 bf16, SW128
    __shared__ __align__(1024) uint8_t smB[2][8192];    // 64 x 64 bf16, SW128

    const int tid = threadIdx.x, l = tid & 31, wid = tid >> 5;
    const int wm = (wid & 3) * 32, wn = (wid >> 2) * 32;
    const int n0 = blockIdx.x * 64, m0 = blockIdx.y * 128;
    const int kz = blockIdx.z * zchunk;
    const int nst = 3 * spp;
    out += (size_t)blockIdx.z * zstride;

    const uint32_t sA0 = smem_u32(smA[0]), sA1 = smem_u32(smA[1]);
    const uint32_t sB0 = smem_u32(smB[0]), sB1 = smem_u32(smB[1]);

    const int arow = tid >> 3;
    const int ach  = (tid & 7) * 8;
    const uint32_t a_sw = SWZ((uint32_t)(tid >> 3) * 128 + (uint32_t)(tid & 7) * 16);
    const uint32_t b_sw = a_sw;
    const __nv_bfloat16* Ag = A + (size_t)(m0 + arow) * kstride + ach;
    const __nv_bfloat16* Bg = B + (size_t)(n0 + arow) * kstride + ach;
    const size_t astep = (size_t)32 * kstride;

    const uint32_t amat_u0 = (uint32_t)(wm + (l & 15)) * 128 + (uint32_t)(l >> 4) * 16;
    const uint32_t amat_u1 = amat_u0 + 16 * 128;
    const uint32_t bmat_u0 = (uint32_t)(wn + (l >> 4) * 8 + (l & 7)) * 128
                           + (uint32_t)((l >> 3) & 1) * 16;
    const uint32_t bmat_u1 = bmat_u0 + 16 * 128;

    float acc[2][4][4];
#pragma unroll
    for (int i = 0; i < 2; ++i)
#pragma unroll
        for (int j = 0; j < 4; ++j)
#pragma unroll
            for (int q = 0; q < 4; ++q) acc[i][j][q] = 0.f;

    uint4 pa[4], pb[2];

#define SWZ_R1 4096
#define SWZ_R2 8192
#define SWZ_R3 12288

#define KAPOS(s, p, i) (((p) == 2 ? Kp : 0) + kz + (i) * 64)
#define KBPOS(s, p, i) (((p) == 1 ? Kp : 0) + kz + (i) * 64)

#define LDG_STAGE(kA, kB)                                                   \
    {                                                                       \
        const __nv_bfloat16* ap = Ag + (kA);                                \
        const __nv_bfloat16* bp = Bg + (kB);                                \
        pa[0] = *(const uint4*)(ap);                                        \
        pa[1] = *(const uint4*)(ap + astep);                                \
        pa[2] = *(const uint4*)(ap + 2 * astep);                            \
        pa[3] = *(const uint4*)(ap + 3 * astep);                            \
        pb[0] = *(const uint4*)(bp);                                        \
        pb[1] = *(const uint4*)(bp + astep);                                \
    }

#define STS_STAGE(st)                                                       \
    {                                                                       \
        uint8_t* da = smA[st];                                              \
        uint8_t* db = smB[st];                                              \
        *(uint4*)(da + a_sw)          = pa[0];                              \
        *(uint4*)(da + a_sw + SWZ_R1) = pa[1];                              \
        *(uint4*)(da + a_sw + SWZ_R2) = pa[2];                              \
        *(uint4*)(da + a_sw + SWZ_R3) = pa[3];                              \
        *(uint4*)(db + b_sw)          = pb[0];                              \
        *(uint4*)(db + b_sw + SWZ_R1) = pb[1];                              \
    }

#define COMPUTE_STAGE(aS, bS)                                               \
    _Pragma("unroll")                                                       \
    for (int kk = 0; kk < 4; ++kk) {                                        \
        const uint32_t koff = (uint32_t)kk * 32;                            \
        uint32_t a0[4], a1[4], b0[4], b1[4];                                \
        asm volatile("ldmatrix.sync.aligned.m8n8.x4.shared.b16 {%0,%1,%2,%3}, [%4];" \
            : "=r"(a0[0]), "=r"(a0[1]), "=r"(a0[2]), "=r"(a0[3])            \
            : "r"((aS) + SWZ(amat_u0 + koff)));                             \
        asm volatile("ldmatrix.sync.aligned.m8n8.x4.shared.b16 {%0,%1,%2,%3}, [%4];" \
            : "=r"(a1[0]), "=r"(a1[1]), "=r"(a1[2]), "=r"(a1[3])            \
            : "r"((aS) + SWZ(amat_u1 + koff)));                             \
        asm volatile("ldmatrix.sync.aligned.m8n8.x4.shared.b16 {%0,%1,%2,%3}, [%4];" \
            : "=r"(b0[0]), "=r"(b0[1]), "=r"(b0[2]), "=r"(b0[3])            \
            : "r"((bS) + SWZ(bmat_u0 + koff)));                             \
        asm volatile("ldmatrix.sync.aligned.m8n8.x4.shared.b16 {%0,%1,%2,%3}, [%4];" \
            : "=r"(b1[0]), "=r"(b1[1]), "=r"(b1[2]), "=r"(b1[3])            \
            : "r"((bS) + SWZ(bmat_u1 + koff)));                             \
        _Pragma("unroll")                                                   \
        for (int mi = 0; mi < 2; ++mi) {                                    \
            const uint32_t* af = mi ? a1 : a0;                              \
            _Pragma("unroll")                                               \
            for (int ni = 0; ni < 4; ++ni) {                                \
                const uint32_t* bf = (ni < 2) ? b0 : b1;                    \
                const int w = (ni & 1) * 2;                                 \
                asm volatile(                                               \
                    "mma.sync.aligned.m16n8k16.row.col.f32.bf16.bf16.f32 "  \
                    "{%0,%1,%2,%3}, {%4,%5,%6,%7}, {%8,%9}, {%0,%1,%2,%3};" \
                    : "+f"(acc[mi][ni][0]), "+f"(acc[mi][ni][1]),           \
                      "+f"(acc[mi][ni][2]), "+f"(acc[mi][ni][3])            \
                    : "r"(af[0]), "r"(af[1]), "r"(af[2]), "r"(af[3]),       \
                      "r"(bf[w]), "r"(bf[w + 1]));                          \
            }                                                               \
        }                                                                   \
    }

    LDG_STAGE(KAPOS(0, 0, 0), KBPOS(0, 0, 0))
    STS_STAGE(0)
    __syncthreads();

    int cur = 0;
#pragma unroll 1
    for (int s = 1; s < nst; ++s) {
        const int p = s / spp, i = s - p * spp;
        LDG_STAGE(KAPOS(s, p, i), KBPOS(s, p, i))
        if (cur == 0) { COMPUTE_STAGE(sA0, sB0) } else { COMPUTE_STAGE(sA1, sB1) }
        STS_STAGE(cur ^ 1)
        __syncthreads();
        cur ^= 1;
    }
    if (cur == 0) { COMPUTE_STAGE(sA0, sB0) } else { COMPUTE_STAGE(sA1, sB1) }

    // Epilogue: m-major float2 stores.
    const int me = m0 + wm + (l >> 2);
    const int ne = n0 + wn + (l & 3) * 2;
#pragma unroll
    for (int mi = 0; mi < 2; ++mi) {
#pragma unroll
        for (int ni = 0; ni < 4; ++ni) {
            const int m = me + mi * 16;
            const int n = ne + ni * 8;
            *(float2*)&out[(size_t)m * out_ld + n] =
                make_float2(acc[mi][ni][0], acc[mi][ni][1]);
            *(float2*)&out[(size_t)(m + 8) * out_ld + n] =
                make_float2(acc[mi][ni][2], acc[mi][ni][3]);
        }
    }
}

// ---------------------------------------------------------------------------
// pack_a2: sum gemm1 split-K partials + bias -> relu -> [hi|lo] bf16.
// 4 elems/thread, finer grid (1280 blocks) to shrink tail effects.
// ---------------------------------------------------------------------------
__global__ void pack_a2(const float* __restrict__ b1) {
    const int n4 = HQ >> 2;
    const int idx = blockIdx.x * 256 + threadIdx.x;
    if (idx >= BQ * n4) return;
    const int m = idx / n4, c4 = (idx - m * n4) << 2;
    const size_t o = (size_t)m * HQ + c4;

    const float4 v0 = *(const float4*)&g_p1[o];
    const float4 u0 = *(const float4*)&g_p1[(size_t)BQ * HQ + o];
    const float4 c0 = *(const float4*)&b1[c4];

    float v[4] = {
        fmaxf(v0.x + u0.x + c0.x, 0.f), fmaxf(v0.y + u0.y + c0.y, 0.f),
        fmaxf(v0.z + u0.z + c0.z, 0.f), fmaxf(v0.w + u0.w + c0.w, 0.f)};

    __align__(8) __nv_bfloat16 hb[4], lb[4];
#pragma unroll
    for (int t = 0; t < 4; ++t) {
        hb[t] = __float2bfloat16(v[t]);
        lb[t] = __float2bfloat16(v[t] - __bfloat162float(hb[t]));
    }
    const size_t base = (size_t)m * 2 * HQ;
    *(uint2*)&g_a2p[base + c4]      = *(uint2*)hb;
    *(uint2*)&g_a2p[base + HQ + c4] = *(uint2*)lb;
}

// ---------------------------------------------------------------------------
// reduce2: sum gemm2 split-K partials [z][m][512] + bias -> g_phi[m][511]
// ---------------------------------------------------------------------------
__global__ void reduce2(const float* __restrict__ b2) {
    const int idx = blockIdx.x * 256 + threadIdx.x;
    if (idx >= BQ * DQ) return;
    const int m = idx / DQ, n = idx - m * DQ;
    float s = b2[n];
#pragma unroll
    for (int z = 0; z < SPLITK2; ++z)
        s += g_p2[(size_t)z * BQ * NQ2 + (size_t)m * NQ2 + n];
    g_phi[idx] = s;
}

// ---------------------------------------------------------------------------
// quad_kernel (SYMMETRIC, upper-triangular): reads only 134 MB.
//   quad = sum_r phi_r * (2 * sum_{j>=r} M_rj phi_j  -  M_rr phi_r)
// Row pairing (r, 510-r) balances ragged rows to exactly 512 elems/pair.
// ---------------------------------------------------------------------------
__global__ __launch_bounds__(256)
void quad_kernel(const float* __restrict__ M) {
    const int b = blockIdx.x;
    const int s = blockIdx.y;
    __shared__ float sphi[512];
    __shared__ float red[8];
    const int tid = threadIdx.x;
    const int lane = tid & 31, w = tid >> 5;

    for (int i = tid; i < 512; i += 256)
        sphi[i] = (i < DQ) ? g_phi[b * DQ + i] : 0.f;
    __syncthreads();

    const float* __restrict__ Mb = M + (size_t)b * DQ * DQ;
    float acc = 0.f;

#pragma unroll 1
    for (int i = w; i < 32; i += 8) {
        const int r1 = s * 32 + i;        // 0..255
        const int r2 = 510 - r1;          // 255..510

        {
            const float* __restrict__ row = Mb + (size_t)r1 * DQ;
            float rs = 0.f;
#pragma unroll 4
            for (int j = r1 + lane; j < DQ; j += 32)
                rs = fmaf(row[j], sphi[j], rs);
            acc = fmaf(sphi[r1], 2.f * rs, acc);
            if (lane == 0)
                acc -= sphi[r1] * row[r1] * sphi[r1];
        }
        if (r2 != r1) {
            const float* __restrict__ row = Mb + (size_t)r2 * DQ;
            float rs = 0.f;
#pragma unroll 4
            for (int j = r2 + lane; j < DQ; j += 32)
                rs = fmaf(row[j], sphi[j], rs);
            acc = fmaf(sphi[r2], 2.f * rs, acc);
            if (lane == 0)
                acc -= sphi[r2] * row[r2] * sphi[r2];
        }
    }

#pragma unroll
    for (int o = 16; o > 0; o >>= 1) acc += __shfl_xor_sync(0xffffffffu, acc, o);
    if (lane == 0) red[w] = acc;
    __syncthreads();
    if (tid == 0) {
        float sum = 0.f;
#pragma unroll
        for (int i = 0; i < 8; ++i) sum += red[i];
        g_quadpart[b * QSPLIT + s] = sum;
    }
}

// ---------------------------------------------------------------------------
// Final elementwise: inline quad-partial sum + soft-threshold (1->5->1 MLP).
// ---------------------------------------------------------------------------
__global__ void final_kernel(const float* __restrict__ sw1, const float* __restrict__ sb1,
                             const float* __restrict__ sw2, const float* __restrict__ sb2,
                             float* __restrict__ out) {
    const int idx = blockIdx.x * blockDim.x + threadIdx.x;
    if (idx >= BQ * DQ) return;
    const int b = idx / DQ;
    float q = 0.f;
#pragma unroll
    for (int i = 0; i < QSPLIT; ++i) q += g_quadpart[b * QSPLIT + i];
    const float pn = g_phi[idx] / sqrtf(q);
    float lam = sb2[0];
#pragma unroll
    for (int i = 0; i < 5; ++i) {
        float g = fmaf(pn, sw1[i], sb1[i]);
        g = g > 0.f ? g : 0.f;
        lam = fmaf(g, sw2[i], lam);
    }
    lam = fabsf(lam) * 0.1f;
    float a = fabsf(pn) - lam;
    a = a > 0.f ? a : 0.f;
    out[idx] = copysignf(a, pn);
}

// ---------------------------------------------------------------------------
extern "C" void kernel_launch(void* const* d_in, const int* in_sizes, int n_in,
                              void* d_out, int out_size) {
    const float* theta12 = (const float*)d_in[0];
    const float* invT    = (const float*)d_in[3];
    const float* w1      = (const float*)d_in[6];
    const float* b1      = (const float*)d_in[7];
    const float* w2      = (const float*)d_in[8];
    const float* b2      = (const float*)d_in[9];
    const float* sw1     = (const float*)d_in[10];
    const float* sb1     = (const float*)d_in[11];
    const float* sw2     = (const float*)d_in[12];
    const float* sb2     = (const float*)d_in[13];
    float* out = (float*)d_out;

    __nv_bfloat16 *a1p, *b1p, *a2p, *b2p;
    float *p1, *p2;
    cudaGetSymbolAddress((void**)&a1p, g_a1p);
    cudaGetSymbolAddress((void**)&b1p, g_b1p);
    cudaGetSymbolAddress((void**)&a2p, g_a2p);
    cudaGetSymbolAddress((void**)&b2p, g_b2p);
    cudaGetSymbolAddress((void**)&p1,  g_p1);
    cudaGetSymbolAddress((void**)&p2,  g_p2);

    // Layer-1 packs ([hi|lo], K 511 -> 512 padded)
    pack_split<<<(BQ * KP1 / 8 + 255) / 256, 256>>>(theta12, a1p, BQ, BQ, DQ, KP1);
    pack_split<<<(HQ * KP1 / 8 + 255) / 256, 256>>>(w1, b1p, HQ, HQ, DQ, KP1);
    // GEMM1: split-K=2, 3-pass bf16-split; out p1 [z][m][5120]
    gemm_mma<<<dim3(HQ / 64, BQ / 128, SPLITK1), 256>>>(
        a1p, b1p, p1, 2 * KP1, KP1, SPP1, KP1 / SPLITK1, HQ, (size_t)BQ * HQ);
    // bias + relu + [hi|lo] split -> a2p
    pack_a2<<<(BQ * HQ / 4 + 255) / 256, 256>>>(b1);
    // W2 pack (rows padded 511 -> 512)
    pack_split<<<(NQ2 * HQ / 8 + 255) / 256, 256>>>(w2, b2p, NQ2, DQ, HQ, HQ);
    // GEMM2: split-K=16, 3-pass; out p2 [z][m][512]
    gemm_mma<<<dim3(NQ2 / 64, BQ / 128, SPLITK2), 256>>>(
        a2p, b2p, p2, 2 * HQ, HQ, SPP2, HQ / SPLITK2, NQ2, (size_t)BQ * NQ2);
    reduce2<<<(BQ * DQ + 255) / 256, 256>>>(b2);

    quad_kernel<<<dim3(BQ, QSPLIT), 256>>>(invT);
    final_kernel<<<(BQ * DQ + 255) / 256, 256>>>(sw1, sb1, sw2, sb2, out);
}

// round 16
// speedup vs baseline: 1.1131x; 1.1131x over previous
#include <cuda_runtime.h>
#include <cuda_bf16.h>
#include <math.h>
#include <stdint.h>

// ---------------------------------------------------------------------------
// Problem constants
// ---------------------------------------------------------------------------
#define BQ 256
#define DQ 511
#define HQ 5120
#define KP1 512                 // padded K, layer 1
#define NQ2 512                 // padded N, layer 2
#define SPLITK1 2
#define SPLITK2 16
#define SPP1 (KP1 / SPLITK1 / 64)   // 4 stages per pass (gemm1)
#define SPP2 (HQ / SPLITK2 / 64)    // 5 stages per pass (gemm2)
#define QSPLIT 8

// ---------------------------------------------------------------------------
// Scratch (__device__ globals; no allocation allowed). Packed layout: [hi|lo].
// ---------------------------------------------------------------------------
__device__ __align__(16) __nv_bfloat16 g_a1p[BQ * 2 * KP1];
__device__ __align__(16) __nv_bfloat16 g_b1p[(size_t)HQ * 2 * KP1];
__device__ __align__(16) float         g_p1[(size_t)SPLITK1 * BQ * HQ];   // [z][m][n]
__device__ __align__(16) __nv_bfloat16 g_a2p[(size_t)BQ * 2 * HQ];
__device__ __align__(16) float         g_p2[(size_t)SPLITK2 * BQ * NQ2];  // [z][m][n]
__device__ __align__(16) float         g_phi[BQ * DQ];
__device__ float g_quadpart[BQ * QSPLIT];

#define SWZ(o) ((o) ^ (((o) >> 3) & 0x70))

__device__ __forceinline__ uint32_t smem_u32(const void* p) {
    uint32_t a;
    asm("{ .reg .u64 t; cvta.to.shared.u64 t, %1; cvt.u32.u64 %0, t; }"
        : "=r"(a) : "l"(p));
    return a;
}

// Convert a float pair to packed bf16x2; lo!=0 -> residual (v - bf16(v)).
__device__ __forceinline__ uint32_t cvt2bf(float x, float y, int lo) {
    __nv_bfloat162 h = __floats2bfloat162_rn(x, y);
    if (lo) {
        const float rx = x - __bfloat162float(__low2bfloat16(h));
        const float ry = y - __bfloat162float(__high2bfloat16(h));
        h = __floats2bfloat162_rn(rx, ry);
    }
    uint32_t u;
    *(__nv_bfloat162*)&u = h;
    return u;
}

// ---------------------------------------------------------------------------
// pack_split: fp32 -> [hi|lo] bf16 segments, 8 elems/thread, 16B stores.
// (kept for theta and W1, whose 511-elem fp32 rows are not 16B-aligned)
// ---------------------------------------------------------------------------
__global__ void pack_split(const float* __restrict__ src, __nv_bfloat16* __restrict__ dst,
                           int nrows, int vrows, int K, int Kp) {
    const int n8 = Kp >> 3;
    const int idx = blockIdx.x * 256 + threadIdx.x;
    if (idx >= nrows * n8) return;
    const int r = idx / n8, c8 = (idx - r * n8) << 3;

    __align__(16) __nv_bfloat16 hb[8], lb[8];
#pragma unroll
    for (int t = 0; t < 8; ++t) {
        const int c = c8 + t;
        const float v = (r < vrows && c < K) ? src[(size_t)r * K + c] : 0.f;
        hb[t] = __float2bfloat16(v);
        lb[t] = __float2bfloat16(v - __bfloat162float(hb[t]));
    }
    const size_t base = (size_t)r * 2 * Kp;
    *(uint4*)&dst[base + c8]      = *(uint4*)hb;
    *(uint4*)&dst[base + Kp + c8] = *(uint4*)lb;
}

// ---------------------------------------------------------------------------
// gemm_mma<BF32>: D[m][n] = sum_k A[m][k]*B[n][k], bf16-split 3-pass schedule:
//   pass0 Ah*Bh, pass1 Ah*Bl, pass2 Al*Bh
// A always packed [hi|lo] bf16 (seg len Kp). B:
//   BF32=0: packed [hi|lo] bf16, row stride kstride
//   BF32=1: raw fp32 (row stride HQ, 16B-aligned); hi/lo produced in-register
//           at STS time -> pack_w2 kernel eliminated.
// Block tile 128m x 64n x 64k, 8 warps, double-buffered smem, occ 2.
// ---------------------------------------------------------------------------
template <int BF32>
__global__ __launch_bounds__(256, 2)
void gemm_mma(const __nv_bfloat16* __restrict__ A, const __nv_bfloat16* __restrict__ B,
              const float* __restrict__ Bf,
              float* __restrict__ out, int kstride, int Kp, int spp,
              int zchunk, int out_ld, size_t zstride) {
    __shared__ __align__(1024) uint8_t smA[2][16384];   // 128 x 64 bf16, SW128
    __shared__ __align__(1024) uint8_t smB[2][8192];    // 64 x 64 bf16, SW128

    const int tid = threadIdx.x, l = tid & 31, wid = tid >> 5;
    const int wm = (wid & 3) * 32, wn = (wid >> 2) * 32;
    const int n0 = blockIdx.x * 64, m0 = blockIdx.y * 128;
    const int kz = blockIdx.z * zchunk;
    const int nst = 3 * spp;
    out += (size_t)blockIdx.z * zstride;

    const uint32_t sA0 = smem_u32(smA[0]), sA1 = smem_u32(smA[1]);
    const uint32_t sB0 = smem_u32(smB[0]), sB1 = smem_u32(smB[1]);

    const int arow = tid >> 3;
    const int ach  = (tid & 7) * 8;
    const uint32_t a_sw = SWZ((uint32_t)(tid >> 3) * 128 + (uint32_t)(tid & 7) * 16);
    const uint32_t b_sw = a_sw;
    const __nv_bfloat16* Ag = A + (size_t)(m0 + arow) * kstride + ach;
    const size_t astep = (size_t)32 * kstride;

    // B loaders
    const __nv_bfloat16* Bg = (BF32 == 0)
        ? B + (size_t)(n0 + arow) * kstride + ach : (const __nv_bfloat16*)0;
    const float *Bf0 = 0, *Bf1 = 0;
    if (BF32) {
        const int bn0 = n0 + arow;              // <= 479 always valid
        const int bn1 = min(bn0 + 32, DQ - 1);  // clamp row 511 -> 510
        Bf0 = Bf + (size_t)bn0 * HQ + ach;
        Bf1 = Bf + (size_t)bn1 * HQ + ach;
    }

    const uint32_t amat_u0 = (uint32_t)(wm + (l & 15)) * 128 + (uint32_t)(l >> 4) * 16;
    const uint32_t amat_u1 = amat_u0 + 16 * 128;
    const uint32_t bmat_u0 = (uint32_t)(wn + (l >> 4) * 8 + (l & 7)) * 128
                           + (uint32_t)((l >> 3) & 1) * 16;
    const uint32_t bmat_u1 = bmat_u0 + 16 * 128;

    float acc[2][4][4];
#pragma unroll
    for (int i = 0; i < 2; ++i)
#pragma unroll
        for (int j = 0; j < 4; ++j)
#pragma unroll
            for (int q = 0; q < 4; ++q) acc[i][j][q] = 0.f;

    uint4 pa[4];
    uint4 pbq[2];
    float4 pbf[4];

#define SWZ_R1 4096
#define SWZ_R2 8192
#define SWZ_R3 12288

#define KAPOS(p, i) (((p) == 2 ? Kp : 0) + kz + (i) * 64)
#define KBPOS(p, i) (((p) == 1 ? Kp : 0) + kz + (i) * 64)   // packed-B only
#define KFPOS(i)    (kz + (i) * 64)                          // fp32-B

#define LDG_STAGE(p, i)                                                     \
    {                                                                       \
        const __nv_bfloat16* ap = Ag + KAPOS(p, i);                         \
        pa[0] = *(const uint4*)(ap);                                        \
        pa[1] = *(const uint4*)(ap + astep);                                \
        pa[2] = *(const uint4*)(ap + 2 * astep);                            \
        pa[3] = *(const uint4*)(ap + 3 * astep);                            \
        if (BF32) {                                                         \
            const float* q0 = Bf0 + KFPOS(i);                               \
            const float* q1 = Bf1 + KFPOS(i);                               \
            pbf[0] = *(const float4*)(q0);                                  \
            pbf[1] = *(const float4*)(q0 + 4);                              \
            pbf[2] = *(const float4*)(q1);                                  \
            pbf[3] = *(const float4*)(q1 + 4);                              \
        } else {                                                            \
            const __nv_bfloat16* bp = Bg + KBPOS(p, i);                     \
            pbq[0] = *(const uint4*)(bp);                                   \
            pbq[1] = *(const uint4*)(bp + astep);                           \
        }                                                                   \
    }

#define STS_STAGE(st, p)                                                    \
    {                                                                       \
        uint8_t* da = smA[st];                                              \
        uint8_t* db = smB[st];                                              \
        *(uint4*)(da + a_sw)          = pa[0];                              \
        *(uint4*)(da + a_sw + SWZ_R1) = pa[1];                              \
        *(uint4*)(da + a_sw + SWZ_R2) = pa[2];                              \
        *(uint4*)(da + a_sw + SWZ_R3) = pa[3];                              \
        if (BF32) {                                                         \
            const int lo = ((p) == 1);                                      \
            uint4 w0, w1;                                                   \
            w0.x = cvt2bf(pbf[0].x, pbf[0].y, lo);                          \
            w0.y = cvt2bf(pbf[0].z, pbf[0].w, lo);                          \
            w0.z = cvt2bf(pbf[1].x, pbf[1].y, lo);                          \
            w0.w = cvt2bf(pbf[1].z, pbf[1].w, lo);                          \
            w1.x = cvt2bf(pbf[2].x, pbf[2].y, lo);                          \
            w1.y = cvt2bf(pbf[2].z, pbf[2].w, lo);                          \
            w1.z = cvt2bf(pbf[3].x, pbf[3].y, lo);                          \
            w1.w = cvt2bf(pbf[3].z, pbf[3].w, lo);                          \
            *(uint4*)(db + b_sw)          = w0;                             \
            *(uint4*)(db + b_sw + SWZ_R1) = w1;                             \
        } else {                                                            \
            *(uint4*)(db + b_sw)          = pbq[0];                         \
            *(uint4*)(db + b_sw + SWZ_R1) = pbq[1];                         \
        }                                                                   \
    }

#define COMPUTE_STAGE(aS, bS)                                               \
    _Pragma("unroll")                                                       \
    for (int kk = 0; kk < 4; ++kk) {                                        \
        const uint32_t koff = (uint32_t)kk * 32;                            \
        uint32_t a0[4], a1[4], b0[4], b1[4];                                \
        asm volatile("ldmatrix.sync.aligned.m8n8.x4.shared.b16 {%0,%1,%2,%3}, [%4];" \
            : "=r"(a0[0]), "=r"(a0[1]), "=r"(a0[2]), "=r"(a0[3])            \
            : "r"((aS) + SWZ(amat_u0 + koff)));                             \
        asm volatile("ldmatrix.sync.aligned.m8n8.x4.shared.b16 {%0,%1,%2,%3}, [%4];" \
            : "=r"(a1[0]), "=r"(a1[1]), "=r"(a1[2]), "=r"(a1[3])            \
            : "r"((aS) + SWZ(amat_u1 + koff)));                             \
        asm volatile("ldmatrix.sync.aligned.m8n8.x4.shared.b16 {%0,%1,%2,%3}, [%4];" \
            : "=r"(b0[0]), "=r"(b0[1]), "=r"(b0[2]), "=r"(b0[3])            \
            : "r"((bS) + SWZ(bmat_u0 + koff)));                             \
        asm volatile("ldmatrix.sync.aligned.m8n8.x4.shared.b16 {%0,%1,%2,%3}, [%4];" \
            : "=r"(b1[0]), "=r"(b1[1]), "=r"(b1[2]), "=r"(b1[3])            \
            : "r"((bS) + SWZ(bmat_u1 + koff)));                             \
        _Pragma("unroll")                                                   \
        for (int mi = 0; mi < 2; ++mi) {                                    \
            const uint32_t* af = mi ? a1 : a0;                              \
            _Pragma("unroll")                                               \
            for (int ni = 0; ni < 4; ++ni) {                                \
                const uint32_t* bf = (ni < 2) ? b0 : b1;                    \
                const int w = (ni & 1) * 2;                                 \
                asm volatile(                                               \
                    "mma.sync.aligned.m16n8k16.row.col.f32.bf16.bf16.f32 "  \
                    "{%0,%1,%2,%3}, {%4,%5,%6,%7}, {%8,%9}, {%0,%1,%2,%3};" \
                    : "+f"(acc[mi][ni][0]), "+f"(acc[mi][ni][1]),           \
                      "+f"(acc[mi][ni][2]), "+f"(acc[mi][ni][3])            \
                    : "r"(af[0]), "r"(af[1]), "r"(af[2]), "r"(af[3]),       \
                      "r"(bf[w]), "r"(bf[w + 1]));                          \
            }                                                               \
        }                                                                   \
    }

    LDG_STAGE(0, 0)
    STS_STAGE(0, 0)
    __syncthreads();

    int cur = 0;
#pragma unroll 1
    for (int s = 1; s < nst; ++s) {
        const int p = s / spp, i = s - p * spp;
        LDG_STAGE(p, i)
        if (cur == 0) { COMPUTE_STAGE(sA0, sB0) } else { COMPUTE_STAGE(sA1, sB1) }
        STS_STAGE(cur ^ 1, p)
        __syncthreads();
        cur ^= 1;
    }
    if (cur == 0) { COMPUTE_STAGE(sA0, sB0) } else { COMPUTE_STAGE(sA1, sB1) }

    // Epilogue: m-major float2 stores.
    const int me = m0 + wm + (l >> 2);
    const int ne = n0 + wn + (l & 3) * 2;
#pragma unroll
    for (int mi = 0; mi < 2; ++mi) {
#pragma unroll
        for (int ni = 0; ni < 4; ++ni) {
            const int m = me + mi * 16;
            const int n = ne + ni * 8;
            *(float2*)&out[(size_t)m * out_ld + n] =
                make_float2(acc[mi][ni][0], acc[mi][ni][1]);
            *(float2*)&out[(size_t)(m + 8) * out_ld + n] =
                make_float2(acc[mi][ni][2], acc[mi][ni][3]);
        }
    }
}

// ---------------------------------------------------------------------------
// pack_a2: sum gemm1 split-K partials + bias -> relu -> [hi|lo] bf16.
// 4 elems/thread (finer grid shrinks tail effects).
// ---------------------------------------------------------------------------
__global__ void pack_a2(const float* __restrict__ b1) {
    const int n4 = HQ >> 2;
    const int idx = blockIdx.x * 256 + threadIdx.x;
    if (idx >= BQ * n4) return;
    const int m = idx / n4, c4 = (idx - m * n4) << 2;
    const size_t o = (size_t)m * HQ + c4;

    const float4 v0 = *(const float4*)&g_p1[o];
    const float4 u0 = *(const float4*)&g_p1[(size_t)BQ * HQ + o];
    const float4 c0 = *(const float4*)&b1[c4];

    float v[4] = {
        fmaxf(v0.x + u0.x + c0.x, 0.f), fmaxf(v0.y + u0.y + c0.y, 0.f),
        fmaxf(v0.z + u0.z + c0.z, 0.f), fmaxf(v0.w + u0.w + c0.w, 0.f)};

    __align__(8) __nv_bfloat16 hb[4], lb[4];
#pragma unroll
    for (int t = 0; t < 4; ++t) {
        hb[t] = __float2bfloat16(v[t]);
        lb[t] = __float2bfloat16(v[t] - __bfloat162float(hb[t]));
    }
    const size_t base = (size_t)m * 2 * HQ;
    *(uint2*)&g_a2p[base + c4]      = *(uint2*)hb;
    *(uint2*)&g_a2p[base + HQ + c4] = *(uint2*)lb;
}

// ---------------------------------------------------------------------------
// reduce2: sum gemm2 split-K partials [z][m][512] + bias -> g_phi[m][511]
// ---------------------------------------------------------------------------
__global__ void reduce2(const float* __restrict__ b2) {
    const int idx = blockIdx.x * 256 + threadIdx.x;
    if (idx >= BQ * DQ) return;
    const int m = idx / DQ, n = idx - m * DQ;
    float s = b2[n];
#pragma unroll
    for (int z = 0; z < SPLITK2; ++z)
        s += g_p2[(size_t)z * BQ * NQ2 + (size_t)m * NQ2 + n];
    g_phi[idx] = s;
}

// ---------------------------------------------------------------------------
// quad_kernel (SYMMETRIC, upper-triangular): reads only 134 MB.
//   quad = sum_r phi_r * (2 * sum_{j>=r} M_rj phi_j  -  M_rr phi_r)
// Row pairing (r, 510-r) balances ragged rows to exactly 512 elems/pair.
// ---------------------------------------------------------------------------
__global__ __launch_bounds__(256)
void quad_kernel(const float* __restrict__ M) {
    const int b = blockIdx.x;
    const int s = blockIdx.y;
    __shared__ float sphi[512];
    __shared__ float red[8];
    const int tid = threadIdx.x;
    const int lane = tid & 31, w = tid >> 5;

    for (int i = tid; i < 512; i += 256)
        sphi[i] = (i < DQ) ? g_phi[b * DQ + i] : 0.f;
    __syncthreads();

    const float* __restrict__ Mb = M + (size_t)b * DQ * DQ;
    float acc = 0.f;

#pragma unroll 1
    for (int i = w; i < 32; i += 8) {
        const int r1 = s * 32 + i;        // 0..255
        const int r2 = 510 - r1;          // 255..510

        {
            const float* __restrict__ row = Mb + (size_t)r1 * DQ;
            float rs = 0.f;
#pragma unroll 4
            for (int j = r1 + lane; j < DQ; j += 32)
                rs = fmaf(row[j], sphi[j], rs);
            acc = fmaf(sphi[r1], 2.f * rs, acc);
            if (lane == 0)
                acc -= sphi[r1] * row[r1] * sphi[r1];
        }
        if (r2 != r1) {
            const float* __restrict__ row = Mb + (size_t)r2 * DQ;
            float rs = 0.f;
#pragma unroll 4
            for (int j = r2 + lane; j < DQ; j += 32)
                rs = fmaf(row[j], sphi[j], rs);
            acc = fmaf(sphi[r2], 2.f * rs, acc);
            if (lane == 0)
                acc -= sphi[r2] * row[r2] * sphi[r2];
        }
    }

#pragma unroll
    for (int o = 16; o > 0; o >>= 1) acc += __shfl_xor_sync(0xffffffffu, acc, o);
    if (lane == 0) red[w] = acc;
    __syncthreads();
    if (tid == 0) {
        float sum = 0.f;
#pragma unroll
        for (int i = 0; i < 8; ++i) sum += red[i];
        g_quadpart[b * QSPLIT + s] = sum;
    }
}

// ---------------------------------------------------------------------------
// Final elementwise: inline quad-partial sum + soft-threshold (1->5->1 MLP).
// ---------------------------------------------------------------------------
__global__ void final_kernel(const float* __restrict__ sw1, const float* __restrict__ sb1,
                             const float* __restrict__ sw2, const float* __restrict__ sb2,
                             float* __restrict__ out) {
    const int idx = blockIdx.x * blockDim.x + threadIdx.x;
    if (idx >= BQ * DQ) return;
    const int b = idx / DQ;
    float q = 0.f;
#pragma unroll
    for (int i = 0; i < QSPLIT; ++i) q += g_quadpart[b * QSPLIT + i];
    const float pn = g_phi[idx] / sqrtf(q);
    float lam = sb2[0];
#pragma unroll
    for (int i = 0; i < 5; ++i) {
        float g = fmaf(pn, sw1[i], sb1[i]);
        g = g > 0.f ? g : 0.f;
        lam = fmaf(g, sw2[i], lam);
    }
    lam = fabsf(lam) * 0.1f;
    float a = fabsf(pn) - lam;
    a = a > 0.f ? a : 0.f;
    out[idx] = copysignf(a, pn);
}

// ---------------------------------------------------------------------------
extern "C" void kernel_launch(void* const* d_in, const int* in_sizes, int n_in,
                              void* d_out, int out_size) {
    const float* theta12 = (const float*)d_in[0];
    const float* invT    = (const float*)d_in[3];
    const float* w1      = (const float*)d_in[6];
    const float* b1      = (const float*)d_in[7];
    const float* w2      = (const float*)d_in[8];
    const float* b2      = (const float*)d_in[9];
    const float* sw1     = (const float*)d_in[10];
    const float* sb1     = (const float*)d_in[11];
    const float* sw2     = (const float*)d_in[12];
    const float* sb2     = (const float*)d_in[13];
    float* out = (float*)d_out;

    __nv_bfloat16 *a1p, *b1p, *a2p;
    float *p1, *p2;
    cudaGetSymbolAddress((void**)&a1p, g_a1p);
    cudaGetSymbolAddress((void**)&b1p, g_b1p);
    cudaGetSymbolAddress((void**)&a2p, g_a2p);
    cudaGetSymbolAddress((void**)&p1,  g_p1);
    cudaGetSymbolAddress((void**)&p2,  g_p2);

    // Layer-1 packs ([hi|lo], K 511 -> 512 padded; rows are misaligned fp32)
    pack_split<<<(BQ * KP1 / 8 + 255) / 256, 256>>>(theta12, a1p, BQ, BQ, DQ, KP1);
    pack_split<<<(HQ * KP1 / 8 + 255) / 256, 256>>>(w1, b1p, HQ, HQ, DQ, KP1);
    // GEMM1: split-K=2, 3-pass bf16-split, packed B; out p1 [z][m][5120]
    gemm_mma<0><<<dim3(HQ / 64, BQ / 128, SPLITK1), 256>>>(
        a1p, b1p, (const float*)0, p1, 2 * KP1, KP1, SPP1, KP1 / SPLITK1, HQ,
        (size_t)BQ * HQ);
    // bias + relu + [hi|lo] split -> a2p
    pack_a2<<<(BQ * HQ / 4 + 255) / 256, 256>>>(b1);
    // GEMM2: split-K=16, 3-pass, B = W2 fp32 direct (in-register hi/lo split)
    gemm_mma<1><<<dim3(NQ2 / 64, BQ / 128, SPLITK2), 256>>>(
        a2p, (const __nv_bfloat16*)0, w2, p2, 2 * HQ, HQ, SPP2, HQ / SPLITK2, NQ2,
        (size_t)BQ * NQ2);
    reduce2<<<(BQ * DQ + 255) / 256, 256>>>(b2);

    quad_kernel<<<dim3(BQ, QSPLIT), 256>>>(invT);
    final_kernel<<<(BQ * DQ + 255) / 256, 256>>>(sw1, sb1, sw2, sb2, out);
}